// round 13
// baseline (speedup 1.0000x reference)
#include <cuda_runtime.h>
#include <math.h>

#define NN 50000
#define EE 800000
#define ALPHA_C 0.1f

// ---------------- scratch (device globals; no allocation allowed) ----------------
__device__ float g_t[NN * 128];    // GEMM output buffer (also reused as N x 40 for conv3)
__device__ float g_h1[NN * 128];   // h1 (post relu)
__device__ float g_c[NN * 128];    // combined h
__device__ float g_d1[NN];         // dinv1 (unit weights)
__device__ float g_d2[NN];         // dinv2 (edge_weight), accumulates deg2 first
__device__ int   g_cnt[NN];        // in-degree counts
__device__ int   g_off[NN + 1];    // CSR offsets (by dst)
__device__ int   g_cur[NN];        // fill cursors
__device__ int   g_esrc[EE];       // CSR: src node per slot
__device__ float g_ewl[EE];        // CSR: edge weight per slot
__device__ int   g_is64;           // edge_index dtype flag

// ---------------- dtype helpers ----------------
__device__ __forceinline__ int load_src(const void* ei, int e) {
    return g_is64 ? (int)((const long long*)ei)[e] : ((const int*)ei)[e];
}
__device__ __forceinline__ int load_dst(const void* ei, int e) {
    return g_is64 ? (int)((const long long*)ei)[EE + e] : ((const int*)ei)[EE + e];
}

// ---------------- prep: zero + dtype detect (merged; block 0 scans dtype) ----------------
__global__ void zero_detect_kernel(const int* ei32) {
    int i = blockIdx.x * blockDim.x + threadIdx.x;
    if (i < NN) { g_cnt[i] = 0; g_d2[i] = 1.0f; }   // self-loop weight 1 for deg2
    if (blockIdx.x == 0) {
        __shared__ int any;
        if (threadIdx.x == 0) any = 0;
        __syncthreads();
        int local = 0;
        for (int k = threadIdx.x; k < 4096; k += blockDim.x)
            if (ei32[2 * k + 1] != 0) local = 1;
        if (local) atomicOr(&any, 1);
        __syncthreads();
        if (threadIdx.x == 0) g_is64 = (any == 0) ? 1 : 0;
    }
}

__global__ void count_kernel(const void* __restrict__ ei, const float* __restrict__ ew) {
    int e = blockIdx.x * blockDim.x + threadIdx.x;
    if (e >= EE) return;
    int d = load_dst(ei, e);
    atomicAdd(&g_cnt[d], 1);
    atomicAdd(&g_d2[d], ew[e]);
}

// single-block scan over 50000 counts -> offsets + cursors; finalizes dinv1/dinv2
__global__ void scan_dinv_kernel() {
    __shared__ int tsum[1024];
    const int CH = (NN + 1023) / 1024;  // 49
    int t = threadIdx.x;
    int beg = t * CH, end = min(beg + CH, NN);
    int s = 0;
    for (int i = beg; i < end; i++) s += g_cnt[i];
    tsum[t] = s;
    __syncthreads();
    for (int off = 1; off < 1024; off <<= 1) {
        int v = (t >= off) ? tsum[t - off] : 0;
        __syncthreads();
        tsum[t] += v;
        __syncthreads();
    }
    int run = (t ? tsum[t - 1] : 0);
    for (int i = beg; i < end; i++) {
        int c = g_cnt[i];
        g_off[i] = run; g_cur[i] = run;
        run += c;
        g_d1[i] = rsqrtf(1.0f + (float)c);   // unit-weight degree incl. self-loop
        g_d2[i] = rsqrtf(g_d2[i]);
    }
    if (beg < NN && end == NN) g_off[NN] = run;
}

__global__ void fill_kernel(const void* __restrict__ ei, const float* __restrict__ ew) {
    int e = blockIdx.x * blockDim.x + threadIdx.x;
    if (e >= EE) return;
    int s = load_src(ei, e);
    int d = load_dst(ei, e);
    int pos = atomicAdd(&g_cur[d], 1);
    g_esrc[pos] = s;
    g_ewl[pos] = ew[e];
}

// ---------------- GEMM: T[NN,C] = dinv[row] * (X[NN,128] @ W[128,C]) ----------------
// R2-proven kernel + row pre-scaling epilogue (dinv[gr] folded into the store).
__global__ void gemm_kernel(const float* __restrict__ X, const float* __restrict__ W,
                            float* __restrict__ T, const float* __restrict__ dinv, int C) {
    __shared__ float Xs[64][33];
    __shared__ float Ws[32][64];
    int tid  = threadIdx.x;
    int row0 = blockIdx.x * 64;
    int col0 = blockIdx.y * 64;
    int c0 = (tid & 15) * 4;
    int r0 = (tid >> 4) * 4;
    float acc[4][4] = {};

    for (int kk = 0; kk < 128; kk += 32) {
        for (int f = tid; f < 512; f += 256) {
            int r = f >> 3, k4 = f & 7;
            int gr = row0 + r;
            float4 v = make_float4(0.f, 0.f, 0.f, 0.f);
            if (gr < NN) v = *(const float4*)(X + (size_t)gr * 128 + kk + k4 * 4);
            Xs[r][k4 * 4 + 0] = v.x; Xs[r][k4 * 4 + 1] = v.y;
            Xs[r][k4 * 4 + 2] = v.z; Xs[r][k4 * 4 + 3] = v.w;
        }
        for (int f = tid; f < 512; f += 256) {
            int k = f >> 4, c4 = f & 15;
            int gc = col0 + c4 * 4;
            float4 v = make_float4(0.f, 0.f, 0.f, 0.f);
            if (gc < C) v = *(const float4*)(W + (size_t)(kk + k) * C + gc);
            *(float4*)&Ws[k][c4 * 4] = v;
        }
        __syncthreads();
        #pragma unroll
        for (int k = 0; k < 32; k++) {
            float4 w = *(const float4*)&Ws[k][c0];
            #pragma unroll
            for (int j = 0; j < 4; j++) {
                float xv = Xs[r0 + j][k];
                acc[j][0] += xv * w.x; acc[j][1] += xv * w.y;
                acc[j][2] += xv * w.z; acc[j][3] += xv * w.w;
            }
        }
        __syncthreads();
    }
    #pragma unroll
    for (int j = 0; j < 4; j++) {
        int gr = row0 + r0 + j;
        int gc = col0 + c0;
        if (gr < NN && gc < C) {
            float s = dinv[gr];
            *(float4*)(T + (size_t)gr * C + gc) =
                make_float4(acc[j][0] * s, acc[j][1] * s, acc[j][2] * s, acc[j][3] * s);
        }
    }
}

// ---------------- fused CSR aggregation, 128-wide (one warp per dst node) ----------------
// T rows are pre-scaled by dinv[src]:
//   OUT[d] = epilogue( dinv[d] * ( T'[d] + sum_e w_e * T'[s] ) + b )
// mode 0: relu(.)           -> h1
// mode 1: 0.1*H1[d] + (.)   -> combined h
__global__ void agg128_kernel(const float* __restrict__ T, float* __restrict__ OUT,
                              const float* __restrict__ dinv, const float* __restrict__ b,
                              const float* __restrict__ H1, int mode, int hasw) {
    int gw = (blockIdx.x * blockDim.x + threadIdx.x) >> 5;
    if (gw >= NN) return;
    int lane = threadIdx.x & 31;
    const float4* T4 = (const float4*)T;

    float dd = dinv[gw];
    float4 acc = T4[(size_t)gw * 32 + lane];   // self-loop term: dd*t[d] = T'[d]

    int beg = g_off[gw], end = g_off[gw + 1];
    for (int i = beg; i < end; i++) {
        int s = g_esrc[i];
        float4 v = T4[(size_t)s * 32 + lane];
        if (hasw) {
            float nw = g_ewl[i];
            acc.x += v.x * nw; acc.y += v.y * nw;
            acc.z += v.z * nw; acc.w += v.w * nw;
        } else {
            acc.x += v.x; acc.y += v.y;
            acc.z += v.z; acc.w += v.w;
        }
    }

    float4 bb = ((const float4*)b)[lane];
    float4 r;
    r.x = acc.x * dd + bb.x; r.y = acc.y * dd + bb.y;
    r.z = acc.z * dd + bb.z; r.w = acc.w * dd + bb.w;
    if (mode == 0) {
        r.x = fmaxf(r.x, 0.f); r.y = fmaxf(r.y, 0.f);
        r.z = fmaxf(r.z, 0.f); r.w = fmaxf(r.w, 0.f);
    } else {
        float4 h = ((const float4*)H1)[(size_t)gw * 32 + lane];
        r.x += ALPHA_C * h.x; r.y += ALPHA_C * h.y;
        r.z += ALPHA_C * h.z; r.w += ALPHA_C * h.w;
    }
    ((float4*)OUT)[(size_t)gw * 32 + lane] = r;
}

// ---------------- fused CSR aggregation 40-wide + bias + log_softmax ----------------
// T rows pre-scaled by dinv1[src]; one warp per node; lanes 0..19 hold float2 each.
__global__ void agg40_lsm_kernel(const float* __restrict__ T, float* __restrict__ OUT,
                                 const float* __restrict__ dinv, const float* __restrict__ b) {
    int gw = (blockIdx.x * blockDim.x + threadIdx.x) >> 5;
    if (gw >= NN) return;
    int lane = threadIdx.x & 31;
    const float2* T2 = (const float2*)T;

    float dd = dinv[gw];
    float2 acc = make_float2(0.f, 0.f);
    if (lane < 20) {
        acc = T2[(size_t)gw * 20 + lane];      // self-loop term (pre-scaled)
    }
    int beg = g_off[gw], end = g_off[gw + 1];
    for (int i = beg; i < end; i++) {
        int s = g_esrc[i];
        if (lane < 20) {
            float2 v = T2[(size_t)s * 20 + lane];
            acc.x += v.x; acc.y += v.y;
        }
    }
    float rx = -1e30f, ry = -1e30f;
    if (lane < 20) {
        float2 bb = ((const float2*)b)[lane];
        rx = acc.x * dd + bb.x;
        ry = acc.y * dd + bb.y;
    }
    float m = fmaxf(rx, ry);
    #pragma unroll
    for (int o = 16; o; o >>= 1) m = fmaxf(m, __shfl_xor_sync(0xffffffffu, m, o));
    float s_ = (lane < 20) ? (expf(rx - m) + expf(ry - m)) : 0.f;
    #pragma unroll
    for (int o = 16; o; o >>= 1) s_ += __shfl_xor_sync(0xffffffffu, s_, o);
    float l = m + logf(s_);
    if (lane < 20)
        ((float2*)OUT)[(size_t)gw * 20 + lane] = make_float2(rx - l, ry - l);
}

// ---------------- launch ----------------
extern "C" void kernel_launch(void* const* d_in, const int* in_sizes, int n_in,
                              void* d_out, int out_size) {
    const float* x  = (const float*)d_in[0];
    const void*  ei = d_in[1];
    const float* ew = (const float*)d_in[2];
    const float* W1 = (const float*)d_in[3];
    const float* b1 = (const float*)d_in[4];
    const float* W2 = (const float*)d_in[5];
    const float* b2 = (const float*)d_in[6];
    const float* W3 = (const float*)d_in[7];
    const float* b3 = (const float*)d_in[8];
    float* out = (float*)d_out;

    float *t, *h1, *c, *d1, *d2;
    cudaGetSymbolAddress((void**)&t,  g_t);
    cudaGetSymbolAddress((void**)&h1, g_h1);
    cudaGetSymbolAddress((void**)&c,  g_c);
    cudaGetSymbolAddress((void**)&d1, g_d1);
    cudaGetSymbolAddress((void**)&d2, g_d2);

    const int TB = 256;
    const int NB_N = (NN + TB - 1) / TB;
    const int NB_E = (EE + TB - 1) / TB;
    const int NB_W = (NN * 32 + TB - 1) / TB;   // one warp per node
    dim3 gg128((NN + 63) / 64, 2);
    dim3 gg40((NN + 63) / 64, 1);

    // graph prep — merged to 4 launches; order otherwise identical to R12
    zero_detect_kernel<<<NB_N, TB>>>((const int*)ei);
    count_kernel<<<NB_E, TB>>>(ei, ew);
    scan_dinv_kernel<<<1, 1024>>>();
    fill_kernel<<<NB_E, TB>>>(ei, ew);

    // conv1: h1 = relu(agg_1(x@W1) + b1)      (T rows pre-scaled by d1)
    gemm_kernel<<<gg128, TB>>>(x, W1, t, d1, 128);
    agg128_kernel<<<NB_W, TB>>>(t, h1, d1, b1, nullptr, 0, 0);

    // conv2 (crf): c = 0.1*h1 + agg_w(h1@W2) + b2   (T rows pre-scaled by d2)
    gemm_kernel<<<gg128, TB>>>(h1, W2, t, d2, 128);
    agg128_kernel<<<NB_W, TB>>>(t, c, d2, b2, h1, 1, 1);

    // conv3: out = log_softmax(agg_1(c@W3) + b3)    (T rows pre-scaled by d1)
    gemm_kernel<<<gg40, TB>>>(c, W3, t, d1, 40);
    agg40_lsm_kernel<<<NB_W, TB>>>(t, out, d1, b3);
}

// round 14
// speedup vs baseline: 1.2043x; 1.2043x over previous
#include <cuda_runtime.h>
#include <math.h>

#define NN 50000
#define EE 800000
#define ALPHA_C 0.1f

// ---------------- scratch (device globals; no allocation allowed) ----------------
__device__ float g_t[NN * 128];    // GEMM output buffer (also reused as N x 40 for conv3)
__device__ float g_h1[NN * 128];   // h1 (post relu)
__device__ float g_c[NN * 128];    // combined h
__device__ float g_d1[NN];         // dinv1 (unit weights)
__device__ float g_d2[NN];         // dinv2 (edge_weight), accumulates deg2 first
__device__ int   g_cnt[NN];        // in-degree counts
__device__ int   g_off[NN + 1];    // CSR offsets (by dst)
__device__ int   g_cur[NN];        // fill cursors
__device__ int   g_esrc[EE];       // CSR: src node per slot
__device__ float g_ewl[EE];        // CSR: edge weight per slot
__device__ int   g_is64;           // edge_index dtype flag

// ---------------- dtype helpers ----------------
__device__ __forceinline__ int load_src(const void* ei, int e) {
    return g_is64 ? (int)((const long long*)ei)[e] : ((const int*)ei)[e];
}
__device__ __forceinline__ int load_dst(const void* ei, int e) {
    return g_is64 ? (int)((const long long*)ei)[EE + e] : ((const int*)ei)[EE + e];
}

// ---------------- prep: zero + dtype detect (merged; block 0 scans dtype) -------------
// Multi-block: no throughput-limited op gets serialized onto one SM.
__global__ void zero_detect_kernel(const int* ei32) {
    int i = blockIdx.x * blockDim.x + threadIdx.x;
    if (i < NN) { g_cnt[i] = 0; g_d2[i] = 1.0f; }   // self-loop weight 1 for deg2
    if (blockIdx.x == 0) {
        __shared__ int any;
        if (threadIdx.x == 0) any = 0;
        __syncthreads();
        int local = 0;
        for (int k = threadIdx.x; k < 4096; k += blockDim.x)
            if (ei32[2 * k + 1] != 0) local = 1;
        if (local) atomicOr(&any, 1);
        __syncthreads();
        if (threadIdx.x == 0) g_is64 = (any == 0) ? 1 : 0;
    }
}

__global__ void count_kernel(const void* __restrict__ ei, const float* __restrict__ ew) {
    int e = blockIdx.x * blockDim.x + threadIdx.x;
    if (e >= EE) return;
    int d = load_dst(ei, e);
    atomicAdd(&g_cnt[d], 1);
    atomicAdd(&g_d2[d], ew[e]);
}

// multi-block: 100k rsqrtf spread across the chip (single-block version cost ~65us!)
__global__ void dinv_kernel() {
    int i = blockIdx.x * blockDim.x + threadIdx.x;
    if (i < NN) {
        g_d1[i] = rsqrtf(1.0f + (float)g_cnt[i]);   // unit-weight degree incl. self-loop
        g_d2[i] = rsqrtf(g_d2[i]);
    }
}

// single-block scan over 50000 counts -> offsets + cursors (int work only, no MUFU)
__global__ void scan_kernel() {
    __shared__ int tsum[1024];
    const int CH = (NN + 1023) / 1024;  // 49
    int t = threadIdx.x;
    int beg = t * CH, end = min(beg + CH, NN);
    int s = 0;
    for (int i = beg; i < end; i++) s += g_cnt[i];
    tsum[t] = s;
    __syncthreads();
    for (int off = 1; off < 1024; off <<= 1) {
        int v = (t >= off) ? tsum[t - off] : 0;
        __syncthreads();
        tsum[t] += v;
        __syncthreads();
    }
    int run = (t ? tsum[t - 1] : 0);
    for (int i = beg; i < end; i++) {
        int c = g_cnt[i];
        g_off[i] = run; g_cur[i] = run;
        run += c;
    }
    if (beg < NN && end == NN) g_off[NN] = run;
}

__global__ void fill_kernel(const void* __restrict__ ei, const float* __restrict__ ew) {
    int e = blockIdx.x * blockDim.x + threadIdx.x;
    if (e >= EE) return;
    int s = load_src(ei, e);
    int d = load_dst(ei, e);
    int pos = atomicAdd(&g_cur[d], 1);
    g_esrc[pos] = s;
    g_ewl[pos] = ew[e];
}

// ---------------- GEMM: T[NN,C] = dinv[row] * (X[NN,128] @ W[128,C]) ----------------
// R2-proven kernel + row pre-scaling epilogue (dinv[gr] folded into the store).
__global__ void gemm_kernel(const float* __restrict__ X, const float* __restrict__ W,
                            float* __restrict__ T, const float* __restrict__ dinv, int C) {
    __shared__ float Xs[64][33];
    __shared__ float Ws[32][64];
    int tid  = threadIdx.x;
    int row0 = blockIdx.x * 64;
    int col0 = blockIdx.y * 64;
    int c0 = (tid & 15) * 4;
    int r0 = (tid >> 4) * 4;
    float acc[4][4] = {};

    for (int kk = 0; kk < 128; kk += 32) {
        for (int f = tid; f < 512; f += 256) {
            int r = f >> 3, k4 = f & 7;
            int gr = row0 + r;
            float4 v = make_float4(0.f, 0.f, 0.f, 0.f);
            if (gr < NN) v = *(const float4*)(X + (size_t)gr * 128 + kk + k4 * 4);
            Xs[r][k4 * 4 + 0] = v.x; Xs[r][k4 * 4 + 1] = v.y;
            Xs[r][k4 * 4 + 2] = v.z; Xs[r][k4 * 4 + 3] = v.w;
        }
        for (int f = tid; f < 512; f += 256) {
            int k = f >> 4, c4 = f & 15;
            int gc = col0 + c4 * 4;
            float4 v = make_float4(0.f, 0.f, 0.f, 0.f);
            if (gc < C) v = *(const float4*)(W + (size_t)(kk + k) * C + gc);
            *(float4*)&Ws[k][c4 * 4] = v;
        }
        __syncthreads();
        #pragma unroll
        for (int k = 0; k < 32; k++) {
            float4 w = *(const float4*)&Ws[k][c0];
            #pragma unroll
            for (int j = 0; j < 4; j++) {
                float xv = Xs[r0 + j][k];
                acc[j][0] += xv * w.x; acc[j][1] += xv * w.y;
                acc[j][2] += xv * w.z; acc[j][3] += xv * w.w;
            }
        }
        __syncthreads();
    }
    #pragma unroll
    for (int j = 0; j < 4; j++) {
        int gr = row0 + r0 + j;
        int gc = col0 + c0;
        if (gr < NN && gc < C) {
            float s = dinv[gr];
            *(float4*)(T + (size_t)gr * C + gc) =
                make_float4(acc[j][0] * s, acc[j][1] * s, acc[j][2] * s, acc[j][3] * s);
        }
    }
}

// ---------------- fused CSR aggregation, 128-wide (one warp per dst node) ----------------
// T rows are pre-scaled by dinv[src]:
//   OUT[d] = epilogue( dinv[d] * ( T'[d] + sum_e w_e * T'[s] ) + b )
// mode 0: relu(.)           -> h1
// mode 1: 0.1*H1[d] + (.)   -> combined h
__global__ void agg128_kernel(const float* __restrict__ T, float* __restrict__ OUT,
                              const float* __restrict__ dinv, const float* __restrict__ b,
                              const float* __restrict__ H1, int mode, int hasw) {
    int gw = (blockIdx.x * blockDim.x + threadIdx.x) >> 5;
    if (gw >= NN) return;
    int lane = threadIdx.x & 31;
    const float4* T4 = (const float4*)T;

    float dd = dinv[gw];
    float4 acc = T4[(size_t)gw * 32 + lane];   // self-loop term: dd*t[d] = T'[d]

    int beg = g_off[gw], end = g_off[gw + 1];
    for (int i = beg; i < end; i++) {
        int s = g_esrc[i];
        float4 v = T4[(size_t)s * 32 + lane];
        if (hasw) {
            float nw = g_ewl[i];
            acc.x += v.x * nw; acc.y += v.y * nw;
            acc.z += v.z * nw; acc.w += v.w * nw;
        } else {
            acc.x += v.x; acc.y += v.y;
            acc.z += v.z; acc.w += v.w;
        }
    }

    float4 bb = ((const float4*)b)[lane];
    float4 r;
    r.x = acc.x * dd + bb.x; r.y = acc.y * dd + bb.y;
    r.z = acc.z * dd + bb.z; r.w = acc.w * dd + bb.w;
    if (mode == 0) {
        r.x = fmaxf(r.x, 0.f); r.y = fmaxf(r.y, 0.f);
        r.z = fmaxf(r.z, 0.f); r.w = fmaxf(r.w, 0.f);
    } else {
        float4 h = ((const float4*)H1)[(size_t)gw * 32 + lane];
        r.x += ALPHA_C * h.x; r.y += ALPHA_C * h.y;
        r.z += ALPHA_C * h.z; r.w += ALPHA_C * h.w;
    }
    ((float4*)OUT)[(size_t)gw * 32 + lane] = r;
}

// ---------------- fused CSR aggregation 40-wide + bias + log_softmax ----------------
// T rows pre-scaled by dinv1[src]; one warp per node; lanes 0..19 hold float2 each.
__global__ void agg40_lsm_kernel(const float* __restrict__ T, float* __restrict__ OUT,
                                 const float* __restrict__ dinv, const float* __restrict__ b) {
    int gw = (blockIdx.x * blockDim.x + threadIdx.x) >> 5;
    if (gw >= NN) return;
    int lane = threadIdx.x & 31;
    const float2* T2 = (const float2*)T;

    float dd = dinv[gw];
    float2 acc = make_float2(0.f, 0.f);
    if (lane < 20) {
        acc = T2[(size_t)gw * 20 + lane];      // self-loop term (pre-scaled)
    }
    int beg = g_off[gw], end = g_off[gw + 1];
    for (int i = beg; i < end; i++) {
        int s = g_esrc[i];
        if (lane < 20) {
            float2 v = T2[(size_t)s * 20 + lane];
            acc.x += v.x; acc.y += v.y;
        }
    }
    float rx = -1e30f, ry = -1e30f;
    if (lane < 20) {
        float2 bb = ((const float2*)b)[lane];
        rx = acc.x * dd + bb.x;
        ry = acc.y * dd + bb.y;
    }
    float m = fmaxf(rx, ry);
    #pragma unroll
    for (int o = 16; o; o >>= 1) m = fmaxf(m, __shfl_xor_sync(0xffffffffu, m, o));
    float s_ = (lane < 20) ? (expf(rx - m) + expf(ry - m)) : 0.f;
    #pragma unroll
    for (int o = 16; o; o >>= 1) s_ += __shfl_xor_sync(0xffffffffu, s_, o);
    float l = m + logf(s_);
    if (lane < 20)
        ((float2*)OUT)[(size_t)gw * 20 + lane] = make_float2(rx - l, ry - l);
}

// ---------------- launch ----------------
extern "C" void kernel_launch(void* const* d_in, const int* in_sizes, int n_in,
                              void* d_out, int out_size) {
    const float* x  = (const float*)d_in[0];
    const void*  ei = d_in[1];
    const float* ew = (const float*)d_in[2];
    const float* W1 = (const float*)d_in[3];
    const float* b1 = (const float*)d_in[4];
    const float* W2 = (const float*)d_in[5];
    const float* b2 = (const float*)d_in[6];
    const float* W3 = (const float*)d_in[7];
    const float* b3 = (const float*)d_in[8];
    float* out = (float*)d_out;

    float *t, *h1, *c, *d1, *d2;
    cudaGetSymbolAddress((void**)&t,  g_t);
    cudaGetSymbolAddress((void**)&h1, g_h1);
    cudaGetSymbolAddress((void**)&c,  g_c);
    cudaGetSymbolAddress((void**)&d1, g_d1);
    cudaGetSymbolAddress((void**)&d2, g_d2);

    const int TB = 256;
    const int NB_N = (NN + TB - 1) / TB;
    const int NB_E = (EE + TB - 1) / TB;
    const int NB_W = (NN * 32 + TB - 1) / TB;   // one warp per node
    dim3 gg128((NN + 63) / 64, 2);
    dim3 gg40((NN + 63) / 64, 1);

    // graph prep — 5 launches (detect folded into multi-block zero; dinv stays multi-block)
    zero_detect_kernel<<<NB_N, TB>>>((const int*)ei);
    count_kernel<<<NB_E, TB>>>(ei, ew);
    dinv_kernel<<<NB_N, TB>>>();
    scan_kernel<<<1, 1024>>>();
    fill_kernel<<<NB_E, TB>>>(ei, ew);

    // conv1: h1 = relu(agg_1(x@W1) + b1)      (T rows pre-scaled by d1)
    gemm_kernel<<<gg128, TB>>>(x, W1, t, d1, 128);
    agg128_kernel<<<NB_W, TB>>>(t, h1, d1, b1, nullptr, 0, 0);

    // conv2 (crf): c = 0.1*h1 + agg_w(h1@W2) + b2   (T rows pre-scaled by d2)
    gemm_kernel<<<gg128, TB>>>(h1, W2, t, d2, 128);
    agg128_kernel<<<NB_W, TB>>>(t, c, d2, b2, h1, 1, 1);

    // conv3: out = log_softmax(agg_1(c@W3) + b3)    (T rows pre-scaled by d1)
    gemm_kernel<<<gg40, TB>>>(c, W3, t, d1, 40);
    agg40_lsm_kernel<<<NB_W, TB>>>(t, out, d1, b3);
}

// round 15
// speedup vs baseline: 1.5205x; 1.2625x over previous
#include <cuda_runtime.h>
#include <math.h>

#define NN 50000
#define EE 800000
#define ALPHA_C 0.1f
#define SCAN_B 1024
#define SCAN_NB ((NN + SCAN_B - 1) / SCAN_B)   // 49

// ---------------- scratch (device globals; no allocation allowed) ----------------
__device__ float g_t[NN * 128];    // GEMM output buffer (also reused as N x 40 for conv3)
__device__ float g_h1[NN * 128];   // h1 (post relu)
__device__ float g_c[NN * 128];    // combined h
__device__ float g_d1[NN];         // dinv1 (unit weights)
__device__ float g_d2[NN];         // dinv2 (edge_weight), accumulates deg2 first
__device__ int   g_cnt[NN];        // in-degree counts
__device__ int   g_off[NN + 1];    // CSR offsets (by dst)
__device__ int   g_cur[NN];        // fill cursors
__device__ int   g_esrc[EE];       // CSR: src node per slot
__device__ float g_ewl[EE];        // CSR: edge weight per slot
__device__ int   g_bsum[SCAN_NB];  // per-block scan totals
__device__ int   g_bpre[SCAN_NB];  // per-block exclusive prefixes
__device__ int   g_is64;           // edge_index dtype flag

// ---------------- dtype helpers ----------------
__device__ __forceinline__ int load_src(const void* ei, int e) {
    return g_is64 ? (int)((const long long*)ei)[e] : ((const int*)ei)[e];
}
__device__ __forceinline__ int load_dst(const void* ei, int e) {
    return g_is64 ? (int)((const long long*)ei)[EE + e] : ((const int*)ei)[EE + e];
}

// ---------------- prep: zero + dtype detect (merged; block 0 scans dtype) -------------
__global__ void zero_detect_kernel(const int* ei32) {
    int i = blockIdx.x * blockDim.x + threadIdx.x;
    if (i < NN) { g_cnt[i] = 0; g_d2[i] = 1.0f; }   // self-loop weight 1 for deg2
    if (blockIdx.x == 0) {
        __shared__ int any;
        if (threadIdx.x == 0) any = 0;
        __syncthreads();
        int local = 0;
        for (int k = threadIdx.x; k < 4096; k += blockDim.x)
            if (ei32[2 * k + 1] != 0) local = 1;
        if (local) atomicOr(&any, 1);
        __syncthreads();
        if (threadIdx.x == 0) g_is64 = (any == 0) ? 1 : 0;
    }
}

__global__ void count_kernel(const void* __restrict__ ei, const float* __restrict__ ew) {
    int e = blockIdx.x * blockDim.x + threadIdx.x;
    if (e >= EE) return;
    int d = load_dst(ei, e);
    atomicAdd(&g_cnt[d], 1);
    atomicAdd(&g_d2[d], ew[e]);
}

// multi-block: 100k rsqrtf spread across the chip
__global__ void dinv_kernel() {
    int i = blockIdx.x * blockDim.x + threadIdx.x;
    if (i < NN) {
        g_d1[i] = rsqrtf(1.0f + (float)g_cnt[i]);   // unit-weight degree incl. self-loop
        g_d2[i] = rsqrtf(g_d2[i]);
    }
}

// ---------------- multi-block scan (replaces the 78us single-block scan) -------------
// phase 1: block-local exclusive prefix into g_off; block totals into g_bsum
__global__ void scan1_kernel() {
    __shared__ int sd[SCAN_B];
    int tid = threadIdx.x;
    int i = blockIdx.x * SCAN_B + tid;
    int c = (i < NN) ? g_cnt[i] : 0;
    sd[tid] = c;
    __syncthreads();
    #pragma unroll
    for (int off = 1; off < SCAN_B; off <<= 1) {
        int v = (tid >= off) ? sd[tid - off] : 0;
        __syncthreads();
        sd[tid] += v;
        __syncthreads();
    }
    if (i < NN) g_off[i] = sd[tid] - c;            // block-local exclusive
    if (tid == SCAN_B - 1) g_bsum[blockIdx.x] = sd[tid];
}

// phase 2: tiny serial scan of 49 block totals (one block)
__global__ void scan2_kernel() {
    __shared__ int s[SCAN_NB];
    int tid = threadIdx.x;
    if (tid < SCAN_NB) s[tid] = g_bsum[tid];
    __syncthreads();
    if (tid == 0) {
        int run = 0;
        for (int b = 0; b < SCAN_NB; b++) {
            g_bpre[b] = run;
            run += s[b];
        }
        g_off[NN] = run;   // == EE
    }
}

// phase 3: add block prefix; mirror into cursors
__global__ void scan3_kernel() {
    int i = blockIdx.x * SCAN_B + threadIdx.x;
    if (i >= NN) return;
    int o = g_off[i] + g_bpre[blockIdx.x];
    g_off[i] = o;
    g_cur[i] = o;
}

__global__ void fill_kernel(const void* __restrict__ ei, const float* __restrict__ ew) {
    int e = blockIdx.x * blockDim.x + threadIdx.x;
    if (e >= EE) return;
    int s = load_src(ei, e);
    int d = load_dst(ei, e);
    int pos = atomicAdd(&g_cur[d], 1);
    g_esrc[pos] = s;
    g_ewl[pos] = ew[e];
}

// ---------------- GEMM: T[NN,C] = dinv[row] * (X[NN,128] @ W[128,C]) ----------------
__global__ void gemm_kernel(const float* __restrict__ X, const float* __restrict__ W,
                            float* __restrict__ T, const float* __restrict__ dinv, int C) {
    __shared__ float Xs[64][33];
    __shared__ float Ws[32][64];
    int tid  = threadIdx.x;
    int row0 = blockIdx.x * 64;
    int col0 = blockIdx.y * 64;
    int c0 = (tid & 15) * 4;
    int r0 = (tid >> 4) * 4;
    float acc[4][4] = {};

    for (int kk = 0; kk < 128; kk += 32) {
        for (int f = tid; f < 512; f += 256) {
            int r = f >> 3, k4 = f & 7;
            int gr = row0 + r;
            float4 v = make_float4(0.f, 0.f, 0.f, 0.f);
            if (gr < NN) v = *(const float4*)(X + (size_t)gr * 128 + kk + k4 * 4);
            Xs[r][k4 * 4 + 0] = v.x; Xs[r][k4 * 4 + 1] = v.y;
            Xs[r][k4 * 4 + 2] = v.z; Xs[r][k4 * 4 + 3] = v.w;
        }
        for (int f = tid; f < 512; f += 256) {
            int k = f >> 4, c4 = f & 15;
            int gc = col0 + c4 * 4;
            float4 v = make_float4(0.f, 0.f, 0.f, 0.f);
            if (gc < C) v = *(const float4*)(W + (size_t)(kk + k) * C + gc);
            *(float4*)&Ws[k][c4 * 4] = v;
        }
        __syncthreads();
        #pragma unroll
        for (int k = 0; k < 32; k++) {
            float4 w = *(const float4*)&Ws[k][c0];
            #pragma unroll
            for (int j = 0; j < 4; j++) {
                float xv = Xs[r0 + j][k];
                acc[j][0] += xv * w.x; acc[j][1] += xv * w.y;
                acc[j][2] += xv * w.z; acc[j][3] += xv * w.w;
            }
        }
        __syncthreads();
    }
    #pragma unroll
    for (int j = 0; j < 4; j++) {
        int gr = row0 + r0 + j;
        int gc = col0 + c0;
        if (gr < NN && gc < C) {
            float s = dinv[gr];
            *(float4*)(T + (size_t)gr * C + gc) =
                make_float4(acc[j][0] * s, acc[j][1] * s, acc[j][2] * s, acc[j][3] * s);
        }
    }
}

// ---------------- fused CSR aggregation, 128-wide (one warp per dst node) ----------------
// T rows pre-scaled by dinv[src]:
//   OUT[d] = epilogue( dinv[d] * ( T'[d] + sum_e w_e * T'[s] ) + b )
__global__ void agg128_kernel(const float* __restrict__ T, float* __restrict__ OUT,
                              const float* __restrict__ dinv, const float* __restrict__ b,
                              const float* __restrict__ H1, int mode, int hasw) {
    int gw = (blockIdx.x * blockDim.x + threadIdx.x) >> 5;
    if (gw >= NN) return;
    int lane = threadIdx.x & 31;
    const float4* T4 = (const float4*)T;

    float dd = dinv[gw];
    float4 acc = T4[(size_t)gw * 32 + lane];   // self-loop term (pre-scaled)

    int beg = g_off[gw], end = g_off[gw + 1];
    for (int i = beg; i < end; i++) {
        int s = g_esrc[i];
        float4 v = T4[(size_t)s * 32 + lane];
        if (hasw) {
            float nw = g_ewl[i];
            acc.x += v.x * nw; acc.y += v.y * nw;
            acc.z += v.z * nw; acc.w += v.w * nw;
        } else {
            acc.x += v.x; acc.y += v.y;
            acc.z += v.z; acc.w += v.w;
        }
    }

    float4 bb = ((const float4*)b)[lane];
    float4 r;
    r.x = acc.x * dd + bb.x; r.y = acc.y * dd + bb.y;
    r.z = acc.z * dd + bb.z; r.w = acc.w * dd + bb.w;
    if (mode == 0) {
        r.x = fmaxf(r.x, 0.f); r.y = fmaxf(r.y, 0.f);
        r.z = fmaxf(r.z, 0.f); r.w = fmaxf(r.w, 0.f);
    } else {
        float4 h = ((const float4*)H1)[(size_t)gw * 32 + lane];
        r.x += ALPHA_C * h.x; r.y += ALPHA_C * h.y;
        r.z += ALPHA_C * h.z; r.w += ALPHA_C * h.w;
    }
    ((float4*)OUT)[(size_t)gw * 32 + lane] = r;
}

// ---------------- fused CSR aggregation 40-wide + bias + log_softmax ----------------
__global__ void agg40_lsm_kernel(const float* __restrict__ T, float* __restrict__ OUT,
                                 const float* __restrict__ dinv, const float* __restrict__ b) {
    int gw = (blockIdx.x * blockDim.x + threadIdx.x) >> 5;
    if (gw >= NN) return;
    int lane = threadIdx.x & 31;
    const float2* T2 = (const float2*)T;

    float dd = dinv[gw];
    float2 acc = make_float2(0.f, 0.f);
    if (lane < 20) {
        acc = T2[(size_t)gw * 20 + lane];      // self-loop term (pre-scaled)
    }
    int beg = g_off[gw], end = g_off[gw + 1];
    for (int i = beg; i < end; i++) {
        int s = g_esrc[i];
        if (lane < 20) {
            float2 v = T2[(size_t)s * 20 + lane];
            acc.x += v.x; acc.y += v.y;
        }
    }
    float rx = -1e30f, ry = -1e30f;
    if (lane < 20) {
        float2 bb = ((const float2*)b)[lane];
        rx = acc.x * dd + bb.x;
        ry = acc.y * dd + bb.y;
    }
    float m = fmaxf(rx, ry);
    #pragma unroll
    for (int o = 16; o; o >>= 1) m = fmaxf(m, __shfl_xor_sync(0xffffffffu, m, o));
    float s_ = (lane < 20) ? (expf(rx - m) + expf(ry - m)) : 0.f;
    #pragma unroll
    for (int o = 16; o; o >>= 1) s_ += __shfl_xor_sync(0xffffffffu, s_, o);
    float l = m + logf(s_);
    if (lane < 20)
        ((float2*)OUT)[(size_t)gw * 20 + lane] = make_float2(rx - l, ry - l);
}

// ---------------- launch ----------------
extern "C" void kernel_launch(void* const* d_in, const int* in_sizes, int n_in,
                              void* d_out, int out_size) {
    const float* x  = (const float*)d_in[0];
    const void*  ei = d_in[1];
    const float* ew = (const float*)d_in[2];
    const float* W1 = (const float*)d_in[3];
    const float* b1 = (const float*)d_in[4];
    const float* W2 = (const float*)d_in[5];
    const float* b2 = (const float*)d_in[6];
    const float* W3 = (const float*)d_in[7];
    const float* b3 = (const float*)d_in[8];
    float* out = (float*)d_out;

    float *t, *h1, *c, *d1, *d2;
    cudaGetSymbolAddress((void**)&t,  g_t);
    cudaGetSymbolAddress((void**)&h1, g_h1);
    cudaGetSymbolAddress((void**)&c,  g_c);
    cudaGetSymbolAddress((void**)&d1, g_d1);
    cudaGetSymbolAddress((void**)&d2, g_d2);

    const int TB = 256;
    const int NB_N = (NN + TB - 1) / TB;
    const int NB_E = (EE + TB - 1) / TB;
    const int NB_W = (NN * 32 + TB - 1) / TB;   // one warp per node
    dim3 gg128((NN + 63) / 64, 2);
    dim3 gg40((NN + 63) / 64, 1);

    // graph prep — multi-block scan replaces the 78us single-block scan
    zero_detect_kernel<<<NB_N, TB>>>((const int*)ei);
    count_kernel<<<NB_E, TB>>>(ei, ew);
    dinv_kernel<<<NB_N, TB>>>();
    scan1_kernel<<<SCAN_NB, SCAN_B>>>();
    scan2_kernel<<<1, 64>>>();
    scan3_kernel<<<SCAN_NB, SCAN_B>>>();
    fill_kernel<<<NB_E, TB>>>(ei, ew);

    // conv1: h1 = relu(agg_1(x@W1) + b1)      (T rows pre-scaled by d1)
    gemm_kernel<<<gg128, TB>>>(x, W1, t, d1, 128);
    agg128_kernel<<<NB_W, TB>>>(t, h1, d1, b1, nullptr, 0, 0);

    // conv2 (crf): c = 0.1*h1 + agg_w(h1@W2) + b2   (T rows pre-scaled by d2)
    gemm_kernel<<<gg128, TB>>>(h1, W2, t, d2, 128);
    agg128_kernel<<<NB_W, TB>>>(t, c, d2, b2, h1, 1, 1);

    // conv3: out = log_softmax(agg_1(c@W3) + b3)    (T rows pre-scaled by d1)
    gemm_kernel<<<gg40, TB>>>(c, W3, t, d1, 40);
    agg40_lsm_kernel<<<NB_W, TB>>>(t, out, d1, b3);
}

// round 16
// speedup vs baseline: 1.5435x; 1.0151x over previous
#include <cuda_runtime.h>
#include <math.h>

#define NN 50000
#define EE 800000
#define ALPHA_C 0.1f
#define SCAN_B 1024
#define SCAN_NB ((NN + SCAN_B - 1) / SCAN_B)   // 49

// ---------------- scratch (device globals; no allocation allowed) ----------------
__device__ float g_t[NN * 128];    // GEMM output buffer (also reused as N x 40 for conv3)
__device__ float g_h1[NN * 128];   // h1 (post relu)
__device__ float g_c[NN * 128];    // combined h
__device__ float g_d1[NN];         // dinv1 (unit weights)
__device__ float g_d2[NN];         // dinv2 (edge_weight), accumulates deg2 first
__device__ int   g_cnt[NN];        // in-degree counts
__device__ int   g_off[NN + 1];    // CSR offsets (by dst)
__device__ int   g_cur[NN];        // fill cursors
__device__ int   g_esrc[EE];       // CSR: src node per slot
__device__ float g_ewl[EE];        // CSR: edge weight per slot
__device__ int   g_bsum[SCAN_NB];  // per-block scan totals
__device__ int   g_is64;           // edge_index dtype flag

// ---------------- dtype helpers ----------------
__device__ __forceinline__ int load_src(const void* ei, int e) {
    return g_is64 ? (int)((const long long*)ei)[e] : ((const int*)ei)[e];
}
__device__ __forceinline__ int load_dst(const void* ei, int e) {
    return g_is64 ? (int)((const long long*)ei)[EE + e] : ((const int*)ei)[EE + e];
}

// ---------------- prep: zero + dtype detect (merged; block 0 scans dtype) -------------
__global__ void zero_detect_kernel(const int* ei32) {
    int i = blockIdx.x * blockDim.x + threadIdx.x;
    if (i < NN) { g_cnt[i] = 0; g_d2[i] = 1.0f; }   // self-loop weight 1 for deg2
    if (blockIdx.x == 0) {
        __shared__ int any;
        if (threadIdx.x == 0) any = 0;
        __syncthreads();
        int local = 0;
        for (int k = threadIdx.x; k < 4096; k += blockDim.x)
            if (ei32[2 * k + 1] != 0) local = 1;
        if (local) atomicOr(&any, 1);
        __syncthreads();
        if (threadIdx.x == 0) g_is64 = (any == 0) ? 1 : 0;
    }
}

__global__ void count_kernel(const void* __restrict__ ei, const float* __restrict__ ew) {
    int e = blockIdx.x * blockDim.x + threadIdx.x;
    if (e >= EE) return;
    int d = load_dst(ei, e);
    atomicAdd(&g_cnt[d], 1);
    atomicAdd(&g_d2[d], ew[e]);
}

// ---------------- multi-block scan ----------------
// phase 1: block-local exclusive prefix into g_off; block totals into g_bsum
__global__ void scan1_kernel() {
    __shared__ int sd[SCAN_B];
    int tid = threadIdx.x;
    int i = blockIdx.x * SCAN_B + tid;
    int c = (i < NN) ? g_cnt[i] : 0;
    sd[tid] = c;
    __syncthreads();
    #pragma unroll
    for (int off = 1; off < SCAN_B; off <<= 1) {
        int v = (tid >= off) ? sd[tid - off] : 0;
        __syncthreads();
        sd[tid] += v;
        __syncthreads();
    }
    if (i < NN) g_off[i] = sd[tid] - c;            // block-local exclusive
    if (tid == SCAN_B - 1) g_bsum[blockIdx.x] = sd[tid];
}

// phase 2 (merged): each block computes its own prefix over g_bsum (<=48 adds),
// adds it, mirrors cursors, and finalizes dinv1/dinv2 (MUFU spread over 49 blocks).
__global__ void scan3_kernel() {
    __shared__ int bpre_s;
    int b = blockIdx.x;
    int tid = threadIdx.x;
    if (tid < 32) {
        int v = 0;
        for (int k = tid; k < b; k += 32) v += g_bsum[k];
        #pragma unroll
        for (int o = 16; o; o >>= 1) v += __shfl_xor_sync(0xffffffffu, v, o);
        if (tid == 0) bpre_s = v;
    }
    __syncthreads();
    int i = b * SCAN_B + tid;
    if (i < NN) {
        int o = g_off[i] + bpre_s;
        g_off[i] = o;
        g_cur[i] = o;
        int c = g_cnt[i];
        g_d1[i] = rsqrtf(1.0f + (float)c);   // unit-weight degree incl. self-loop
        g_d2[i] = rsqrtf(g_d2[i]);
    }
    if (b == SCAN_NB - 1 && tid == 0)
        g_off[NN] = bpre_s + g_bsum[b];      // == EE
}

__global__ void fill_kernel(const void* __restrict__ ei, const float* __restrict__ ew) {
    int e = blockIdx.x * blockDim.x + threadIdx.x;
    if (e >= EE) return;
    int s = load_src(ei, e);
    int d = load_dst(ei, e);
    int pos = atomicAdd(&g_cur[d], 1);
    g_esrc[pos] = s;
    g_ewl[pos] = ew[e];
}

// ---------------- GEMM 128: T[NN,128] = dinv[row] * (X[NN,128] @ W[128,128]) ----------
__global__ void gemm_kernel(const float* __restrict__ X, const float* __restrict__ W,
                            float* __restrict__ T, const float* __restrict__ dinv, int C) {
    __shared__ float Xs[64][33];
    __shared__ float Ws[32][64];
    int tid  = threadIdx.x;
    int row0 = blockIdx.x * 64;
    int col0 = blockIdx.y * 64;
    int c0 = (tid & 15) * 4;
    int r0 = (tid >> 4) * 4;
    float acc[4][4] = {};

    for (int kk = 0; kk < 128; kk += 32) {
        for (int f = tid; f < 512; f += 256) {
            int r = f >> 3, k4 = f & 7;
            int gr = row0 + r;
            float4 v = make_float4(0.f, 0.f, 0.f, 0.f);
            if (gr < NN) v = *(const float4*)(X + (size_t)gr * 128 + kk + k4 * 4);
            Xs[r][k4 * 4 + 0] = v.x; Xs[r][k4 * 4 + 1] = v.y;
            Xs[r][k4 * 4 + 2] = v.z; Xs[r][k4 * 4 + 3] = v.w;
        }
        for (int f = tid; f < 512; f += 256) {
            int k = f >> 4, c4 = f & 15;
            int gc = col0 + c4 * 4;
            float4 v = make_float4(0.f, 0.f, 0.f, 0.f);
            if (gc < C) v = *(const float4*)(W + (size_t)(kk + k) * C + gc);
            *(float4*)&Ws[k][c4 * 4] = v;
        }
        __syncthreads();
        #pragma unroll
        for (int k = 0; k < 32; k++) {
            float4 w = *(const float4*)&Ws[k][c0];
            #pragma unroll
            for (int j = 0; j < 4; j++) {
                float xv = Xs[r0 + j][k];
                acc[j][0] += xv * w.x; acc[j][1] += xv * w.y;
                acc[j][2] += xv * w.z; acc[j][3] += xv * w.w;
            }
        }
        __syncthreads();
    }
    #pragma unroll
    for (int j = 0; j < 4; j++) {
        int gr = row0 + r0 + j;
        int gc = col0 + c0;
        if (gr < NN && gc < C) {
            float s = dinv[gr];
            *(float4*)(T + (size_t)gr * C + gc) =
                make_float4(acc[j][0] * s, acc[j][1] * s, acc[j][2] * s, acc[j][3] * s);
        }
    }
}

// ---------------- GEMM 40: warp-aligned column mapping (warps 5-7 skip FMA) ----------
// col-group = tid>>4 (warp-major), row-group = tid&15; col groups 10-15 are entirely
// inside warps 5-7, which skip the inner loop as whole warps.
__global__ void gemm40_kernel(const float* __restrict__ X, const float* __restrict__ W,
                              float* __restrict__ T, const float* __restrict__ dinv) {
    const int C = 40;
    __shared__ float Xs[64][33];
    __shared__ float Ws[32][64];
    int tid  = threadIdx.x;
    int row0 = blockIdx.x * 64;
    int c0 = (tid >> 4) * 4;    // warp-major columns
    int r0 = (tid & 15) * 4;
    float acc[4][4] = {};
    bool live = (c0 < C);

    for (int kk = 0; kk < 128; kk += 32) {
        for (int f = tid; f < 512; f += 256) {
            int r = f >> 3, k4 = f & 7;
            int gr = row0 + r;
            float4 v = make_float4(0.f, 0.f, 0.f, 0.f);
            if (gr < NN) v = *(const float4*)(X + (size_t)gr * 128 + kk + k4 * 4);
            Xs[r][k4 * 4 + 0] = v.x; Xs[r][k4 * 4 + 1] = v.y;
            Xs[r][k4 * 4 + 2] = v.z; Xs[r][k4 * 4 + 3] = v.w;
        }
        for (int f = tid; f < 512; f += 256) {
            int k = f >> 4, c4 = f & 15;
            int gc = c4 * 4;
            float4 v = make_float4(0.f, 0.f, 0.f, 0.f);
            if (gc < C) v = *(const float4*)(W + (size_t)(kk + k) * C + gc);
            *(float4*)&Ws[k][c4 * 4] = v;
        }
        __syncthreads();
        if (live) {
            #pragma unroll
            for (int k = 0; k < 32; k++) {
                float4 w = *(const float4*)&Ws[k][c0];
                #pragma unroll
                for (int j = 0; j < 4; j++) {
                    float xv = Xs[r0 + j][k];
                    acc[j][0] += xv * w.x; acc[j][1] += xv * w.y;
                    acc[j][2] += xv * w.z; acc[j][3] += xv * w.w;
                }
            }
        }
        __syncthreads();
    }
    if (live) {
        #pragma unroll
        for (int j = 0; j < 4; j++) {
            int gr = row0 + r0 + j;
            if (gr < NN) {
                float s = dinv[gr];
                *(float4*)(T + (size_t)gr * C + c0) =
                    make_float4(acc[j][0] * s, acc[j][1] * s, acc[j][2] * s, acc[j][3] * s);
            }
        }
    }
}

// ---------------- fused CSR aggregation, 128-wide (one warp per dst node) ----------------
// T rows pre-scaled by dinv[src]:
//   OUT[d] = epilogue( dinv[d] * ( T'[d] + sum_e w_e * T'[s] ) + b )
__global__ void agg128_kernel(const float* __restrict__ T, float* __restrict__ OUT,
                              const float* __restrict__ dinv, const float* __restrict__ b,
                              const float* __restrict__ H1, int mode, int hasw) {
    int gw = (blockIdx.x * blockDim.x + threadIdx.x) >> 5;
    if (gw >= NN) return;
    int lane = threadIdx.x & 31;
    const float4* T4 = (const float4*)T;

    float dd = dinv[gw];
    float4 acc = T4[(size_t)gw * 32 + lane];   // self-loop term (pre-scaled)

    int beg = g_off[gw], end = g_off[gw + 1];
    for (int i = beg; i < end; i++) {
        int s = g_esrc[i];
        float4 v = T4[(size_t)s * 32 + lane];
        if (hasw) {
            float nw = g_ewl[i];
            acc.x += v.x * nw; acc.y += v.y * nw;
            acc.z += v.z * nw; acc.w += v.w * nw;
        } else {
            acc.x += v.x; acc.y += v.y;
            acc.z += v.z; acc.w += v.w;
        }
    }

    float4 bb = ((const float4*)b)[lane];
    float4 r;
    r.x = acc.x * dd + bb.x; r.y = acc.y * dd + bb.y;
    r.z = acc.z * dd + bb.z; r.w = acc.w * dd + bb.w;
    if (mode == 0) {
        r.x = fmaxf(r.x, 0.f); r.y = fmaxf(r.y, 0.f);
        r.z = fmaxf(r.z, 0.f); r.w = fmaxf(r.w, 0.f);
    } else {
        float4 h = ((const float4*)H1)[(size_t)gw * 32 + lane];
        r.x += ALPHA_C * h.x; r.y += ALPHA_C * h.y;
        r.z += ALPHA_C * h.z; r.w += ALPHA_C * h.w;
    }
    ((float4*)OUT)[(size_t)gw * 32 + lane] = r;
}

// ---------------- fused CSR aggregation 40-wide + bias + log_softmax ----------------
__global__ void agg40_lsm_kernel(const float* __restrict__ T, float* __restrict__ OUT,
                                 const float* __restrict__ dinv, const float* __restrict__ b) {
    int gw = (blockIdx.x * blockDim.x + threadIdx.x) >> 5;
    if (gw >= NN) return;
    int lane = threadIdx.x & 31;
    const float2* T2 = (const float2*)T;

    float dd = dinv[gw];
    float2 acc = make_float2(0.f, 0.f);
    if (lane < 20) {
        acc = T2[(size_t)gw * 20 + lane];      // self-loop term (pre-scaled)
    }
    int beg = g_off[gw], end = g_off[gw + 1];
    for (int i = beg; i < end; i++) {
        int s = g_esrc[i];
        if (lane < 20) {
            float2 v = T2[(size_t)s * 20 + lane];
            acc.x += v.x; acc.y += v.y;
        }
    }
    float rx = -1e30f, ry = -1e30f;
    if (lane < 20) {
        float2 bb = ((const float2*)b)[lane];
        rx = acc.x * dd + bb.x;
        ry = acc.y * dd + bb.y;
    }
    float m = fmaxf(rx, ry);
    #pragma unroll
    for (int o = 16; o; o >>= 1) m = fmaxf(m, __shfl_xor_sync(0xffffffffu, m, o));
    float s_ = (lane < 20) ? (expf(rx - m) + expf(ry - m)) : 0.f;
    #pragma unroll
    for (int o = 16; o; o >>= 1) s_ += __shfl_xor_sync(0xffffffffu, s_, o);
    float l = m + logf(s_);
    if (lane < 20)
        ((float2*)OUT)[(size_t)gw * 20 + lane] = make_float2(rx - l, ry - l);
}

// ---------------- launch ----------------
extern "C" void kernel_launch(void* const* d_in, const int* in_sizes, int n_in,
                              void* d_out, int out_size) {
    const float* x  = (const float*)d_in[0];
    const void*  ei = d_in[1];
    const float* ew = (const float*)d_in[2];
    const float* W1 = (const float*)d_in[3];
    const float* b1 = (const float*)d_in[4];
    const float* W2 = (const float*)d_in[5];
    const float* b2 = (const float*)d_in[6];
    const float* W3 = (const float*)d_in[7];
    const float* b3 = (const float*)d_in[8];
    float* out = (float*)d_out;

    float *t, *h1, *c, *d1, *d2;
    cudaGetSymbolAddress((void**)&t,  g_t);
    cudaGetSymbolAddress((void**)&h1, g_h1);
    cudaGetSymbolAddress((void**)&c,  g_c);
    cudaGetSymbolAddress((void**)&d1, g_d1);
    cudaGetSymbolAddress((void**)&d2, g_d2);

    const int TB = 256;
    const int NB_N = (NN + TB - 1) / TB;
    const int NB_E = (EE + TB - 1) / TB;
    const int NB_W = (NN * 32 + TB - 1) / TB;   // one warp per node
    dim3 gg128((NN + 63) / 64, 2);
    dim3 gg40((NN + 63) / 64, 1);

    // graph prep — 5 launches (scan2+dinv folded into scan3)
    zero_detect_kernel<<<NB_N, TB>>>((const int*)ei);
    count_kernel<<<NB_E, TB>>>(ei, ew);
    scan1_kernel<<<SCAN_NB, SCAN_B>>>();
    scan3_kernel<<<SCAN_NB, SCAN_B>>>();
    fill_kernel<<<NB_E, TB>>>(ei, ew);

    // conv1: h1 = relu(agg_1(x@W1) + b1)      (T rows pre-scaled by d1)
    gemm_kernel<<<gg128, TB>>>(x, W1, t, d1, 128);
    agg128_kernel<<<NB_W, TB>>>(t, h1, d1, b1, nullptr, 0, 0);

    // conv2 (crf): c = 0.1*h1 + agg_w(h1@W2) + b2   (T rows pre-scaled by d2)
    gemm_kernel<<<gg128, TB>>>(h1, W2, t, d2, 128);
    agg128_kernel<<<NB_W, TB>>>(t, c, d2, b2, h1, 1, 1);

    // conv3: out = log_softmax(agg_1(c@W3) + b3)    (T rows pre-scaled by d1)
    gemm40_kernel<<<gg40, TB>>>(c, W3, t, d1);
    agg40_lsm_kernel<<<NB_W, TB>>>(t, out, d1, b3);
}

// round 17
// speedup vs baseline: 1.6304x; 1.0563x over previous
#include <cuda_runtime.h>
#include <math.h>

#define NN 50000
#define EE 800000
#define ALPHA_C 0.1f
#define SCAN_B 1024
#define SCAN_NB ((NN + SCAN_B - 1) / SCAN_B)   // 49

// ---------------- scratch (device globals; no allocation allowed) ----------------
__device__ float g_t[NN * 128];
__device__ float g_h1[NN * 128];
__device__ float g_c[NN * 128];
__device__ float g_d1[NN];
__device__ float g_d2[NN];
__device__ int   g_cnt[NN];
__device__ int   g_off[NN + 1];
__device__ int   g_cur[NN];
__device__ int   g_esrc[EE];
__device__ float g_ewl[EE];
__device__ int   g_bsum[SCAN_NB];
__device__ int   g_is64;

// ---------------- dtype helpers ----------------
__device__ __forceinline__ int load_src(const void* ei, int e) {
    return g_is64 ? (int)((const long long*)ei)[e] : ((const int*)ei)[e];
}
__device__ __forceinline__ int load_dst(const void* ei, int e) {
    return g_is64 ? (int)((const long long*)ei)[EE + e] : ((const int*)ei)[EE + e];
}

// ---------------- prep: zero + dtype detect (merged; block 0 scans dtype) -------------
__global__ void zero_detect_kernel(const int* ei32) {
    int i = blockIdx.x * blockDim.x + threadIdx.x;
    if (i < NN) { g_cnt[i] = 0; g_d2[i] = 1.0f; }
    if (blockIdx.x == 0) {
        __shared__ int any;
        if (threadIdx.x == 0) any = 0;
        __syncthreads();
        int local = 0;
        for (int k = threadIdx.x; k < 4096; k += blockDim.x)
            if (ei32[2 * k + 1] != 0) local = 1;
        if (local) atomicOr(&any, 1);
        __syncthreads();
        if (threadIdx.x == 0) g_is64 = (any == 0) ? 1 : 0;
    }
}

__global__ void count_kernel(const void* __restrict__ ei, const float* __restrict__ ew) {
    int e = blockIdx.x * blockDim.x + threadIdx.x;
    if (e >= EE) return;
    int d = load_dst(ei, e);
    atomicAdd(&g_cnt[d], 1);
    atomicAdd(&g_d2[d], ew[e]);
}

// ---------------- multi-block scan ----------------
__global__ void scan1_kernel() {
    __shared__ int sd[SCAN_B];
    int tid = threadIdx.x;
    int i = blockIdx.x * SCAN_B + tid;
    int c = (i < NN) ? g_cnt[i] : 0;
    sd[tid] = c;
    __syncthreads();
    #pragma unroll
    for (int off = 1; off < SCAN_B; off <<= 1) {
        int v = (tid >= off) ? sd[tid - off] : 0;
        __syncthreads();
        sd[tid] += v;
        __syncthreads();
    }
    if (i < NN) g_off[i] = sd[tid] - c;
    if (tid == SCAN_B - 1) g_bsum[blockIdx.x] = sd[tid];
}

// merged phase 2+3 + dinv finalize
__global__ void scan3_kernel() {
    __shared__ int bpre_s;
    int b = blockIdx.x;
    int tid = threadIdx.x;
    if (tid < 32) {
        int v = 0;
        for (int k = tid; k < b; k += 32) v += g_bsum[k];
        #pragma unroll
        for (int o = 16; o; o >>= 1) v += __shfl_xor_sync(0xffffffffu, v, o);
        if (tid == 0) bpre_s = v;
    }
    __syncthreads();
    int i = b * SCAN_B + tid;
    if (i < NN) {
        int o = g_off[i] + bpre_s;
        g_off[i] = o;
        g_cur[i] = o;
        int c = g_cnt[i];
        g_d1[i] = rsqrtf(1.0f + (float)c);
        g_d2[i] = rsqrtf(g_d2[i]);
    }
    if (b == SCAN_NB - 1 && tid == 0)
        g_off[NN] = bpre_s + g_bsum[b];
}

__global__ void fill_kernel(const void* __restrict__ ei, const float* __restrict__ ew) {
    int e = blockIdx.x * blockDim.x + threadIdx.x;
    if (e >= EE) return;
    int s = load_src(ei, e);
    int d = load_dst(ei, e);
    int pos = atomicAdd(&g_cur[d], 1);
    g_esrc[pos] = s;
    g_ewl[pos] = ew[e];
}

// ---------------- GEMM 128: T = [dinv[row] *] (X @ W); dinv==nullptr -> raw ----------
__global__ void gemm_kernel(const float* __restrict__ X, const float* __restrict__ W,
                            float* __restrict__ T, const float* __restrict__ dinv, int C) {
    __shared__ float Xs[64][33];
    __shared__ float Ws[32][64];
    int tid  = threadIdx.x;
    int row0 = blockIdx.x * 64;
    int col0 = blockIdx.y * 64;
    int c0 = (tid & 15) * 4;
    int r0 = (tid >> 4) * 4;
    float acc[4][4] = {};

    for (int kk = 0; kk < 128; kk += 32) {
        for (int f = tid; f < 512; f += 256) {
            int r = f >> 3, k4 = f & 7;
            int gr = row0 + r;
            float4 v = make_float4(0.f, 0.f, 0.f, 0.f);
            if (gr < NN) v = *(const float4*)(X + (size_t)gr * 128 + kk + k4 * 4);
            Xs[r][k4 * 4 + 0] = v.x; Xs[r][k4 * 4 + 1] = v.y;
            Xs[r][k4 * 4 + 2] = v.z; Xs[r][k4 * 4 + 3] = v.w;
        }
        for (int f = tid; f < 512; f += 256) {
            int k = f >> 4, c4 = f & 15;
            int gc = col0 + c4 * 4;
            float4 v = make_float4(0.f, 0.f, 0.f, 0.f);
            if (gc < C) v = *(const float4*)(W + (size_t)(kk + k) * C + gc);
            *(float4*)&Ws[k][c4 * 4] = v;
        }
        __syncthreads();
        #pragma unroll
        for (int k = 0; k < 32; k++) {
            float4 w = *(const float4*)&Ws[k][c0];
            #pragma unroll
            for (int j = 0; j < 4; j++) {
                float xv = Xs[r0 + j][k];
                acc[j][0] += xv * w.x; acc[j][1] += xv * w.y;
                acc[j][2] += xv * w.z; acc[j][3] += xv * w.w;
            }
        }
        __syncthreads();
    }
    #pragma unroll
    for (int j = 0; j < 4; j++) {
        int gr = row0 + r0 + j;
        int gc = col0 + c0;
        if (gr < NN && gc < C) {
            float s = dinv ? dinv[gr] : 1.0f;
            *(float4*)(T + (size_t)gr * C + gc) =
                make_float4(acc[j][0] * s, acc[j][1] * s, acc[j][2] * s, acc[j][3] * s);
        }
    }
}

// ---------------- GEMM 40: warp-aligned column mapping ----------
__global__ void gemm40_kernel(const float* __restrict__ X, const float* __restrict__ W,
                              float* __restrict__ T, const float* __restrict__ dinv) {
    const int C = 40;
    __shared__ float Xs[64][33];
    __shared__ float Ws[32][64];
    int tid  = threadIdx.x;
    int row0 = blockIdx.x * 64;
    int c0 = (tid >> 4) * 4;
    int r0 = (tid & 15) * 4;
    float acc[4][4] = {};
    bool live = (c0 < C);

    for (int kk = 0; kk < 128; kk += 32) {
        for (int f = tid; f < 512; f += 256) {
            int r = f >> 3, k4 = f & 7;
            int gr = row0 + r;
            float4 v = make_float4(0.f, 0.f, 0.f, 0.f);
            if (gr < NN) v = *(const float4*)(X + (size_t)gr * 128 + kk + k4 * 4);
            Xs[r][k4 * 4 + 0] = v.x; Xs[r][k4 * 4 + 1] = v.y;
            Xs[r][k4 * 4 + 2] = v.z; Xs[r][k4 * 4 + 3] = v.w;
        }
        for (int f = tid; f < 512; f += 256) {
            int k = f >> 4, c4 = f & 15;
            int gc = c4 * 4;
            float4 v = make_float4(0.f, 0.f, 0.f, 0.f);
            if (gc < C) v = *(const float4*)(W + (size_t)(kk + k) * C + gc);
            *(float4*)&Ws[k][c4 * 4] = v;
        }
        __syncthreads();
        if (live) {
            #pragma unroll
            for (int k = 0; k < 32; k++) {
                float4 w = *(const float4*)&Ws[k][c0];
                #pragma unroll
                for (int j = 0; j < 4; j++) {
                    float xv = Xs[r0 + j][k];
                    acc[j][0] += xv * w.x; acc[j][1] += xv * w.y;
                    acc[j][2] += xv * w.z; acc[j][3] += xv * w.w;
                }
            }
        }
        __syncthreads();
    }
    if (live) {
        #pragma unroll
        for (int j = 0; j < 4; j++) {
            int gr = row0 + r0 + j;
            if (gr < NN) {
                float s = dinv[gr];
                *(float4*)(T + (size_t)gr * C + c0) =
                    make_float4(acc[j][0] * s, acc[j][1] * s, acc[j][2] * s, acc[j][3] * s);
            }
        }
    }
}

// ---------------- fused CSR aggregation, 128-wide (one warp per dst node) ------------
// presc=1: T rows pre-scaled by dinv[src] -> edge term w_e * T'[s]
// presc=0: T raw -> edge term dinv[s] * T[s], self term dd*T[d]
__global__ void agg128_kernel(const float* __restrict__ T, float* __restrict__ OUT,
                              const float* __restrict__ dinv, const float* __restrict__ b,
                              const float* __restrict__ H1, int mode, int hasw, int presc) {
    int gw = (blockIdx.x * blockDim.x + threadIdx.x) >> 5;
    if (gw >= NN) return;
    int lane = threadIdx.x & 31;
    const float4* T4 = (const float4*)T;

    float dd = dinv[gw];
    float4 acc = T4[(size_t)gw * 32 + lane];
    if (!presc) { acc.x *= dd; acc.y *= dd; acc.z *= dd; acc.w *= dd; }

    int beg = g_off[gw], end = g_off[gw + 1];
    if (presc) {
        for (int i = beg; i < end; i++) {
            int s = g_esrc[i];
            float4 v = T4[(size_t)s * 32 + lane];
            if (hasw) {
                float nw = g_ewl[i];
                acc.x += v.x * nw; acc.y += v.y * nw;
                acc.z += v.z * nw; acc.w += v.w * nw;
            } else {
                acc.x += v.x; acc.y += v.y;
                acc.z += v.z; acc.w += v.w;
            }
        }
    } else {
        for (int i = beg; i < end; i++) {
            int s = g_esrc[i];
            float nw = dinv[s];
            if (hasw) nw *= g_ewl[i];
            float4 v = T4[(size_t)s * 32 + lane];
            acc.x += v.x * nw; acc.y += v.y * nw;
            acc.z += v.z * nw; acc.w += v.w * nw;
        }
    }

    float4 bb = ((const float4*)b)[lane];
    float4 r;
    r.x = acc.x * dd + bb.x; r.y = acc.y * dd + bb.y;
    r.z = acc.z * dd + bb.z; r.w = acc.w * dd + bb.w;
    if (mode == 0) {
        r.x = fmaxf(r.x, 0.f); r.y = fmaxf(r.y, 0.f);
        r.z = fmaxf(r.z, 0.f); r.w = fmaxf(r.w, 0.f);
    } else {
        float4 h = ((const float4*)H1)[(size_t)gw * 32 + lane];
        r.x += ALPHA_C * h.x; r.y += ALPHA_C * h.y;
        r.z += ALPHA_C * h.z; r.w += ALPHA_C * h.w;
    }
    ((float4*)OUT)[(size_t)gw * 32 + lane] = r;
}

// ---------------- fused CSR aggregation 40-wide + bias + log_softmax ----------------
__global__ void agg40_lsm_kernel(const float* __restrict__ T, float* __restrict__ OUT,
                                 const float* __restrict__ dinv, const float* __restrict__ b) {
    int gw = (blockIdx.x * blockDim.x + threadIdx.x) >> 5;
    if (gw >= NN) return;
    int lane = threadIdx.x & 31;
    const float2* T2 = (const float2*)T;

    float dd = dinv[gw];
    float2 acc = make_float2(0.f, 0.f);
    if (lane < 20) {
        acc = T2[(size_t)gw * 20 + lane];
    }
    int beg = g_off[gw], end = g_off[gw + 1];
    for (int i = beg; i < end; i++) {
        int s = g_esrc[i];
        if (lane < 20) {
            float2 v = T2[(size_t)s * 20 + lane];
            acc.x += v.x; acc.y += v.y;
        }
    }
    float rx = -1e30f, ry = -1e30f;
    if (lane < 20) {
        float2 bb = ((const float2*)b)[lane];
        rx = acc.x * dd + bb.x;
        ry = acc.y * dd + bb.y;
    }
    float m = fmaxf(rx, ry);
    #pragma unroll
    for (int o = 16; o; o >>= 1) m = fmaxf(m, __shfl_xor_sync(0xffffffffu, m, o));
    float s_ = (lane < 20) ? (expf(rx - m) + expf(ry - m)) : 0.f;
    #pragma unroll
    for (int o = 16; o; o >>= 1) s_ += __shfl_xor_sync(0xffffffffu, s_, o);
    float l = m + logf(s_);
    if (lane < 20)
        ((float2*)OUT)[(size_t)gw * 20 + lane] = make_float2(rx - l, ry - l);
}

// ---------------- launch ----------------
extern "C" void kernel_launch(void* const* d_in, const int* in_sizes, int n_in,
                              void* d_out, int out_size) {
    const float* x  = (const float*)d_in[0];
    const void*  ei = d_in[1];
    const float* ew = (const float*)d_in[2];
    const float* W1 = (const float*)d_in[3];
    const float* b1 = (const float*)d_in[4];
    const float* W2 = (const float*)d_in[5];
    const float* b2 = (const float*)d_in[6];
    const float* W3 = (const float*)d_in[7];
    const float* b3 = (const float*)d_in[8];
    float* out = (float*)d_out;

    float *t, *h1, *c, *d1, *d2;
    cudaGetSymbolAddress((void**)&t,  g_t);
    cudaGetSymbolAddress((void**)&h1, g_h1);
    cudaGetSymbolAddress((void**)&c,  g_c);
    cudaGetSymbolAddress((void**)&d1, g_d1);
    cudaGetSymbolAddress((void**)&d2, g_d2);

    const int TB = 256;
    const int NB_N = (NN + TB - 1) / TB;
    const int NB_E = (EE + TB - 1) / TB;
    const int NB_W = (NN * 32 + TB - 1) / TB;
    dim3 gg128((NN + 63) / 64, 2);
    dim3 gg40((NN + 63) / 64, 1);

    // fork/join objects (host-side only; created per call, few calls total)
    cudaStream_t s2;
    cudaEvent_t evF, evJ;
    cudaStreamCreateWithFlags(&s2, cudaStreamNonBlocking);
    cudaEventCreateWithFlags(&evF, cudaEventDisableTiming);
    cudaEventCreateWithFlags(&evJ, cudaEventDisableTiming);

    // fork: gemm1 (raw, no prescale -> depends only on x,W1) runs on s2,
    // concurrent with the whole prep chain on the main stream.
    cudaEventRecord(evF, 0);
    cudaStreamWaitEvent(s2, evF, 0);
    gemm_kernel<<<gg128, TB, 0, s2>>>(x, W1, t, nullptr, 128);
    cudaEventRecord(evJ, s2);

    // prep chain (main stream)
    zero_detect_kernel<<<NB_N, TB>>>((const int*)ei);
    count_kernel<<<NB_E, TB>>>(ei, ew);
    scan1_kernel<<<SCAN_NB, SCAN_B>>>();
    scan3_kernel<<<SCAN_NB, SCAN_B>>>();
    fill_kernel<<<NB_E, TB>>>(ei, ew);

    // join: agg1 needs both prep (off/esrc/d1) and gemm1 (t)
    cudaStreamWaitEvent(0, evJ, 0);

    // conv1: h1 = relu(agg_1(x@W1) + b1)   (raw T -> dinv[s] gather path)
    agg128_kernel<<<NB_W, TB>>>(t, h1, d1, b1, nullptr, 0, 0, 0);

    // conv2 (crf): c = 0.1*h1 + agg_w(h1@W2) + b2   (pre-scaled by d2)
    gemm_kernel<<<gg128, TB>>>(h1, W2, t, d2, 128);
    agg128_kernel<<<NB_W, TB>>>(t, c, d2, b2, h1, 1, 1, 1);

    // conv3: out = log_softmax(agg_1(c@W3) + b3)    (pre-scaled by d1)
    gemm40_kernel<<<gg40, TB>>>(c, W3, t, d1);
    agg40_lsm_kernel<<<NB_W, TB>>>(t, out, d1, b3);
}